// round 13
// baseline (speedup 1.0000x reference)
#include <cuda_runtime.h>
#include <math.h>

#define MAXB 4096
__device__ float g_seg_bce[MAXB];   // zero-init at module load; finalize re-zeroes
__device__ float g_seg_cnt[MAXB];

__device__ __forceinline__ float bce_fast(float p, float t) {
    float lp = fmaxf(__logf(p),        -100.0f);   // __logf(0) = -inf -> -100
    float lq = fmaxf(__logf(1.0f - p), -100.0f);
    return -(t * lp + (1.0f - t) * lq);
}

// ---- node kernel: endpoint-probe batch check (batch traffic /8 on fast path) ----
__global__ void __launch_bounds__(256) node_kernel(
        const float4* __restrict__ pred4,
        const float4* __restrict__ tgt4,
        const int*    __restrict__ batch,
        const int4*   __restrict__ mask4,
        const float*  __restrict__ sat_p,
        const float*  __restrict__ sat_t,
        float*        __restrict__ out,
        int n4, int B, float l1)
{
    const unsigned FULL = 0xffffffffu;

    // block 0: zero out[0], then add saturation term (overlaps main stream)
    if (blockIdx.x == 0) {
        if (threadIdx.x == 0) out[0] = 0.0f;
        __syncthreads();
        float s = 0.0f;
        for (int j = threadIdx.x; j < B; j += blockDim.x)
            s += bce_fast(sat_p[j], sat_t[j]);
        s *= l1 / (float)B;
        #pragma unroll
        for (int o = 16; o; o >>= 1) s += __shfl_down_sync(FULL, s, o);
        if ((threadIdx.x & 31) == 0) atomicAdd(out, s);
    }

    int i = blockIdx.x * blockDim.x + threadIdx.x;
    if (i >= n4) return;

    int lane = threadIdx.x & 31;
    unsigned act = __activemask();

    float4 p4 = __ldcs(&pred4[i]);
    float4 t4 = __ldcs(&tgt4[i]);
    int4   k4 = __ldcs(&mask4[i]);

    int   im = (k4.x + k4.y) + (k4.z + k4.w);
    float m0 = (float)k4.x, m1 = (float)k4.y, m2 = (float)k4.z, m3 = (float)k4.w;
    float b0 = bce_fast(p4.x * m0, t4.x);
    float b1 = bce_fast(p4.y * m1, t4.y);
    float b2 = bce_fast(p4.z * m2, t4.z);
    float b3 = bce_fast(p4.w * m3, t4.w);

    if (act == FULL) {
        // endpoint probe: 2 scalar loads per warp instead of 128 values
        int base_node = (i - lane) << 2;               // first node of this warp
        int sv = 0;
        if (lane == 0)  sv = __ldcs(&batch[base_node]);
        if (lane == 31) sv = __ldcs(&batch[base_node + 127]);
        int wlo = __shfl_sync(FULL, sv, 0);
        int whi = __shfl_sync(FULL, sv, 31);
        if (wlo == whi) {
            // uniform warp: 128 contiguous nodes in one segment
            float b = (b0 + b1) + (b2 + b3);
            int  ws = __reduce_add_sync(FULL, im);
            #pragma unroll
            for (int o = 16; o; o >>= 1)
                b += __shfl_down_sync(FULL, b, o);
            if (lane == 0) {
                atomicAdd(&g_seg_bce[wlo], b);
                atomicAdd(&g_seg_cnt[wlo], (float)ws);
            }
            return;
        }
    }

    // slow path (boundary / partial warps): full per-lane batch read
    const int4* batch4 = (const int4*)batch;
    int4 s4 = __ldcs(&batch4[i]);
    if (s4.x == s4.w) {
        atomicAdd(&g_seg_bce[s4.x], (b0 + b1) + (b2 + b3));
        atomicAdd(&g_seg_cnt[s4.x], (float)im);
    } else {
        atomicAdd(&g_seg_bce[s4.x], b0); atomicAdd(&g_seg_cnt[s4.x], m0);
        atomicAdd(&g_seg_bce[s4.y], b1); atomicAdd(&g_seg_cnt[s4.y], m1);
        atomicAdd(&g_seg_bce[s4.z], b2); atomicAdd(&g_seg_cnt[s4.z], m2);
        atomicAdd(&g_seg_bce[s4.w], b3); atomicAdd(&g_seg_cnt[s4.w], m3);
    }
}

// scalar tail (N % 4)
__global__ void tail_kernel(const float* __restrict__ pred,
                            const float* __restrict__ tgt,
                            const int*   __restrict__ batch,
                            const int*   __restrict__ mask,
                            int start, int n)
{
    int i = start + blockIdx.x * blockDim.x + threadIdx.x;
    if (i >= n) return;
    float m = (float)mask[i];
    atomicAdd(&g_seg_bce[batch[i]], bce_fast(pred[i] * m, tgt[i]));
    atomicAdd(&g_seg_cnt[batch[i]], m);
}

// ---- finalize: only L2-resident g_seg data; 8 blocks, REDG into out ----
__global__ void __launch_bounds__(256) finalize_kernel(float* __restrict__ out, int B)
{
    const unsigned FULL = 0xffffffffu;
    __shared__ float sh[8];

    float acc = 0.0f;
    for (int i = blockIdx.x * blockDim.x + threadIdx.x; i < B;
         i += gridDim.x * blockDim.x) {
        float c  = g_seg_cnt[i];
        float sb = g_seg_bce[i];
        acc += (c > 0.0f) ? (sb / fmaxf(c, 1.0f)) : 0.0f;
        g_seg_cnt[i] = 0.0f;            // re-zero for next graph replay
        g_seg_bce[i] = 0.0f;
    }
    #pragma unroll
    for (int o = 16; o; o >>= 1) acc += __shfl_down_sync(FULL, acc, o);
    int lane = threadIdx.x & 31, wid = threadIdx.x >> 5;
    if (lane == 0) sh[wid] = acc;
    __syncthreads();
    if (wid == 0) {
        acc = (lane < (int)(blockDim.x >> 5)) ? sh[lane] : 0.0f;
        #pragma unroll
        for (int o = 16; o; o >>= 1) acc += __shfl_down_sync(FULL, acc, o);
        if (lane == 0) atomicAdd(out, acc);
    }
}

extern "C" void kernel_launch(void* const* d_in, const int* in_sizes, int n_in,
                              void* d_out, int out_size) {
    const float* y_mus_pred = (const float*)d_in[0];
    const float* y_mus      = (const float*)d_in[1];
    const float* y_sat_pred = (const float*)d_in[2];
    const float* y_sat      = (const float*)d_in[3];
    const int*   batch      = (const int*)  d_in[4];
    const int*   mask       = (const int*)  d_in[5];
    int N = in_sizes[0];
    int B = in_sizes[2];
    float L1 = 1.0f / 50.0f;

    int n4 = N >> 2;
    int blocks = (n4 + 255) / 256;
    if (blocks < 1) blocks = 1;
    node_kernel<<<blocks, 256>>>((const float4*)y_mus_pred,
                                 (const float4*)y_mus,
                                 batch,
                                 (const int4*)mask,
                                 y_sat_pred, y_sat,
                                 (float*)d_out, n4, B, L1);

    int tail_start = n4 << 2;
    if (tail_start < N) {
        tail_kernel<<<1, 256>>>(y_mus_pred, y_mus, batch, mask, tail_start, N);
    }

    finalize_kernel<<<8, 256>>>((float*)d_out, B);
}